// round 9
// baseline (speedup 1.0000x reference)
#include <cuda_runtime.h>

#define M_SLOTS 16
#define KEY_DIM 1024
#define TPB     256

// Cross-block handshake. Zero-initialized at load; last block of every
// launch resets it so each graph replay starts clean (deterministic).
__device__ float        g_wbuf[M_SLOTS];
__device__ unsigned int g_flag;   // 0 = not ready, 1 = weights published
__device__ unsigned int g_done;   // completion counter for reset

// ---------------------------------------------------------------------------
// Phase A (block 0 only), kept out-of-line so its register pressure spills
// locally and cannot inflate the streaming path's allocation.
// 8 warps x 2 slots; cosine sims -> softmax -> g_wbuf, release flag.
// ---------------------------------------------------------------------------
__device__ __noinline__ void compute_weights(const float* __restrict__ task_emb,
                                             const float* __restrict__ K_memory,
                                             float* s_w) {
    __shared__ float s_cos[M_SLOTS];
    const int tid  = threadIdx.x;
    const int warp = tid >> 5;
    const int lane = tid & 31;
    const int sa = 2 * warp, sb = 2 * warp + 1;

    const float4* t4 = (const float4*)task_emb;
    const float4* ka = (const float4*)(K_memory + sa * KEY_DIM);
    const float4* kb = (const float4*)(K_memory + sb * KEY_DIM);

    float dota = 0.f, dotb = 0.f, kka = 0.f, kkb = 0.f, tt = 0.f;
    #pragma unroll
    for (int j = 0; j < 8; j++) {
        float4 t = t4[lane + 32 * j];
        float4 a = ka[lane + 32 * j];
        float4 b = kb[lane + 32 * j];
        dota = fmaf(t.x, a.x, dota); dota = fmaf(t.y, a.y, dota);
        dota = fmaf(t.z, a.z, dota); dota = fmaf(t.w, a.w, dota);
        dotb = fmaf(t.x, b.x, dotb); dotb = fmaf(t.y, b.y, dotb);
        dotb = fmaf(t.z, b.z, dotb); dotb = fmaf(t.w, b.w, dotb);
        kka  = fmaf(a.x, a.x, kka);  kka  = fmaf(a.y, a.y, kka);
        kka  = fmaf(a.z, a.z, kka);  kka  = fmaf(a.w, a.w, kka);
        kkb  = fmaf(b.x, b.x, kkb);  kkb  = fmaf(b.y, b.y, kkb);
        kkb  = fmaf(b.z, b.z, kkb);  kkb  = fmaf(b.w, b.w, kkb);
        tt   = fmaf(t.x, t.x, tt);   tt   = fmaf(t.y, t.y, tt);
        tt   = fmaf(t.z, t.z, tt);   tt   = fmaf(t.w, t.w, tt);
    }
    #pragma unroll
    for (int off = 16; off > 0; off >>= 1) {
        dota += __shfl_down_sync(0xffffffffu, dota, off);
        dotb += __shfl_down_sync(0xffffffffu, dotb, off);
        kka  += __shfl_down_sync(0xffffffffu, kka,  off);
        kkb  += __shfl_down_sync(0xffffffffu, kkb,  off);
        tt   += __shfl_down_sync(0xffffffffu, tt,   off);
    }
    if (lane == 0) {
        float n1 = sqrtf(tt);
        s_cos[sa] = dota / fmaxf(n1 * sqrtf(kka), 1e-6f);
        s_cos[sb] = dotb / fmaxf(n1 * sqrtf(kkb), 1e-6f);
    }
    __syncthreads();

    if (tid == 0) {
        float c[M_SLOTS];
        float mx = -1e30f;
        #pragma unroll
        for (int m = 0; m < M_SLOTS; m++) { c[m] = s_cos[m]; mx = fmaxf(mx, c[m]); }
        float sum = 0.f;
        #pragma unroll
        for (int m = 0; m < M_SLOTS; m++) { c[m] = __expf(c[m] - mx); sum += c[m]; }
        float inv = 1.0f / sum;
        #pragma unroll
        for (int m = 0; m < M_SLOTS; m++) {
            float wm = c[m] * inv;
            s_w[m]    = wm;
            g_wbuf[m] = wm;
        }
        __threadfence();
        unsigned int* fp = &g_flag;
        asm volatile("st.release.gpu.u32 [%0], %1;" :: "l"(fp), "r"(1u) : "memory");
    }
    __syncthreads();
}

// ---------------------------------------------------------------------------
// Single fused kernel. Streaming path is byte-identical to the proven
// 53.8us/82.8%-DRAM loop; handshake adds only a spin (no prefetch, no
// register growth — __launch_bounds__(256, 8) pins the allocation).
// ---------------------------------------------------------------------------
__global__ void __launch_bounds__(TPB, 8) fused_kernel(
        const float*  __restrict__ task_emb,
        const float*  __restrict__ K_memory,
        const float4* __restrict__ V0,
        const float4* __restrict__ V1,
        float4*       __restrict__ out,
        int nv4_0, int nv4_1) {
    __shared__ float s_w[M_SLOTS];
    const int tid = threadIdx.x;

    if (blockIdx.x == 0) {
        compute_weights(task_emb, K_memory, s_w);
    } else {
        if (tid == 0) {
            unsigned int* fp = &g_flag;
            unsigned int f;
            do {
                asm volatile("ld.acquire.gpu.u32 %0, [%1];" : "=r"(f) : "l"(fp) : "memory");
                if (f) break;
                __nanosleep(128);
            } while (true);
        }
        __syncthreads();                    // tid0's acquire orders the reads below
        if (tid < M_SLOTS) s_w[tid] = g_wbuf[tid];
        __syncthreads();
    }

    // ---------------- streaming weighted sum (R5-proven body) ----------------
    const int i = blockIdx.x * TPB + tid;   // grid is an exact fit
    const float4* __restrict__ V;
    size_t stride;
    int idx;
    if (i < nv4_0) { V = V0; idx = i;          stride = (size_t)nv4_0; }
    else           { V = V1; idx = i - nv4_0;  stride = (size_t)nv4_1; }

    float4 acc = make_float4(0.f, 0.f, 0.f, 0.f);
    #pragma unroll
    for (int m = 0; m < M_SLOTS; m++) {
        float4 v = V[(size_t)m * stride + (size_t)idx];
        float wm = s_w[m];
        acc.x = fmaf(wm, v.x, acc.x);
        acc.y = fmaf(wm, v.y, acc.y);
        acc.z = fmaf(wm, v.z, acc.z);
        acc.w = fmaf(wm, v.w, acc.w);
    }
    out[i] = acc;

    // ---------------- reset handshake for the next graph replay --------------
    if (tid == 0) {
        __threadfence();
        unsigned int d = atomicAdd(&g_done, 1u);
        if (d == gridDim.x - 1) {           // last block: all spins have passed
            g_done = 0;
            g_flag = 0;
        }
    }
}

// ---------------------------------------------------------------------------
// Launch contract
// Inputs (metadata order): task_emb [1,1024] f32, K_memory [16,1024] f32,
//                          V0 [16,1024,1024] f32, V1 [16,1024,4096] f32
// Output: rec0 [1024,1024] f32 followed by rec1 [1024,4096] f32
// ---------------------------------------------------------------------------
extern "C" void kernel_launch(void* const* d_in, const int* in_sizes, int n_in,
                              void* d_out, int out_size) {
    const float* task_emb = (const float*)d_in[0];
    const float* K_memory = (const float*)d_in[1];
    const float* V0       = (const float*)d_in[2];
    const float* V1       = (const float*)d_in[3];
    float* out = (float*)d_out;

    const int n0 = in_sizes[2] / M_SLOTS;   // 1024*1024
    const int n1 = in_sizes[3] / M_SLOTS;   // 1024*4096
    const int nv4_0 = n0 / 4;               // 262144
    const int nv4_1 = n1 / 4;               // 1048576
    const int total = nv4_0 + nv4_1;        // 1310720 = 5120 * 256 exactly

    fused_kernel<<<total / TPB, TPB>>>(task_emb, K_memory,
                                       (const float4*)V0, (const float4*)V1,
                                       (float4*)out, nv4_0, nv4_1);
}